// round 12
// baseline (speedup 1.0000x reference)
#include <cuda_runtime.h>
#include <cuda_fp16.h>
#include <stdint.h>

// ---------------- device scratch ----------------
__device__ float    g_W1[128 * 384];          // qkv 1x1 weights, transposed [c][o]
__device__ uint32_t g_Wh[24 * 216 * 128];     // dw 3x3 weights, fp16 A-fragment order (half2)
__device__ float    g_Wp[128 * 128];          // po 1x1 weights, transposed [c][o]
__device__ float    g_qkv1[2 * 384 * 16384];  // after 1x1 conv (NCHW)
__device__ uint32_t g_xth[2 * 16384 * 192];   // [b][y*128+x][c/2] half2
__device__ float    g_qkv2[2 * 384 * 16384];  // after 3x3 conv (NCHW)
__device__ float    g_rnorm[2 * 256];
__device__ float    g_part[2 * 4 * 32 * 1024];
__device__ float    g_attn[2 * 4 * 32 * 32];
__device__ float    g_aout[2 * 128 * 16384];

__constant__ int   c_src[16] = {0,1,2,3, 1,0,3,2, 2,3,0,1, 3,2,1,0};
__constant__ float c_sgn[16] = {1,-1,-1,-1, 1,1,-1,1, 1,1,1,-1, 1,-1,1,1};

static __device__ __forceinline__ void mma16(float* d, const uint32_t* a,
                                             uint32_t b0, uint32_t b1) {
    asm volatile(
        "mma.sync.aligned.m16n8k16.row.col.f32.f16.f16.f32 "
        "{%0,%1,%2,%3}, {%4,%5,%6,%7}, {%8,%9}, {%0,%1,%2,%3};"
        : "+f"(d[0]), "+f"(d[1]), "+f"(d[2]), "+f"(d[3])
        : "r"(a[0]), "r"(a[1]), "r"(a[2]), "r"(a[3]), "r"(b0), "r"(b1));
}
static __device__ __forceinline__ void ldsm4(uint32_t* r, uint32_t addr) {
    asm volatile("ldmatrix.sync.aligned.m8n8.x4.shared.b16 {%0,%1,%2,%3}, [%4];"
        : "=r"(r[0]), "=r"(r[1]), "=r"(r[2]), "=r"(r[3]) : "r"(addr));
}
static __device__ __forceinline__ uint32_t smem_u32(const void* p) {
    uint32_t a;
    asm("{ .reg .u64 t; cvta.to.shared.u64 t, %1; cvt.u32.u64 %0, t; }" : "=r"(a) : "l"(p));
    return a;
}

// ---------------- build quaternion weight matrices ----------------
// g_Wh half2 layout: idx = ((octile*216 + kstep)*32 + lane)*4 + j, halves e=0,1
//   oc = octile*16 + (lane>>2) + (j&1)*8
//   kk = kstep*16 + (lane&3)*2 + e + (j>>1)*8,  kk = kx*1152 + ky*384 + c
__global__ void build_weights(
    const float* __restrict__ qr, const float* __restrict__ qi,
    const float* __restrict__ qj, const float* __restrict__ qk,
    const float* __restrict__ dr, const float* __restrict__ di,
    const float* __restrict__ dj, const float* __restrict__ dk,
    const float* __restrict__ pr, const float* __restrict__ pi,
    const float* __restrict__ pj, const float* __restrict__ pk)
{
    const float* qb[4] = {qr, qi, qj, qk};
    const float* db[4] = {dr, di, dj, dk};
    const float* pb[4] = {pr, pi, pj, pk};
    const int N1 = 128 * 384;
    const int NH = 24 * 216 * 128;     // packed half2 elements
    const int NP = 128 * 128;
    int total = N1 + NH + NP;
    for (int i = blockIdx.x * blockDim.x + threadIdx.x; i < total;
         i += gridDim.x * blockDim.x) {
        if (i < N1) {
            int o = i % 384, c = i / 384;
            int br = o / 96, oo = o % 96, bc = c / 32, cc = c % 32;
            int hi = br * 4 + bc;
            g_W1[i] = c_sgn[hi] * qb[c_src[hi]][oo * 32 + cc];
        } else if (i < N1 + NH) {
            int idx = i - N1;
            int j = idx & 3, lane = (idx >> 2) & 31;
            int rest = idx >> 7;
            int kstep = rest % 216, octile = rest / 216;
            int oc = octile * 16 + (lane >> 2) + (j & 1) * 8;
            float w[2];
            #pragma unroll
            for (int e = 0; e < 2; e++) {
                int kk = kstep * 16 + (lane & 3) * 2 + e + ((j >> 1) << 3);
                int kx = kk / 1152, rem = kk % 1152;
                int ky = rem / 384, c = rem % 384;
                int br = oc / 96, oo = oc % 96, bc = c / 96, cc = c % 96;
                int hi = br * 4 + bc;
                w[e] = c_sgn[hi] * db[c_src[hi]][(oo * 96 + cc) * 9 + ky * 3 + kx];
            }
            __half2 h = __floats2half2_rn(w[0], w[1]);
            g_Wh[idx] = *(uint32_t*)&h;
        } else {
            int idx = i - N1 - NH;
            int o = idx % 128, c = idx / 128;
            int br = o / 32, oo = o % 32, bc = c / 32, cc = c % 32;
            int hi = br * 4 + bc;
            g_Wp[idx] = c_sgn[hi] * pb[c_src[hi]][oo * 32 + cc];
        }
    }
}

// ---------------- 1x1 conv = tiled SGEMM (fp32) ----------------
__global__ __launch_bounds__(256) void gemm1x1(
    int wsel, const float* __restrict__ X, const float* __restrict__ bias,
    float* __restrict__ Y, int M, int K)
{
    __shared__ __align__(16) float Ws[16][64];
    __shared__ __align__(16) float Xs[16][64];
    const float* Wt = wsel ? g_Wp : g_W1;
    int m0 = blockIdx.y * 64;
    int n  = blockIdx.x * 64;
    int b  = n >> 14; int p0 = n & 16383;
    const float* Xb = X + (size_t)b * K * 16384 + p0;
    float* Yb = Y + (size_t)b * M * 16384 + p0;
    int t = threadIdx.x;
    int tx = t & 15, ty = t >> 4;
    float acc[4][4] = {};
    for (int k0 = 0; k0 < K; k0 += 16) {
        #pragma unroll
        for (int i = t; i < 1024; i += 256) {
            int mm = i & 63, kk = i >> 6;
            Ws[kk][mm] = Wt[(size_t)(k0 + kk) * M + m0 + mm];
            Xs[kk][mm] = Xb[(size_t)(k0 + kk) * 16384 + mm];
        }
        __syncthreads();
        #pragma unroll
        for (int kk = 0; kk < 16; kk++) {
            float4 a4 = *(const float4*)&Ws[kk][ty * 4];
            float4 b4 = *(const float4*)&Xs[kk][tx * 4];
            float a_[4] = {a4.x, a4.y, a4.z, a4.w};
            float b_[4] = {b4.x, b4.y, b4.z, b4.w};
            #pragma unroll
            for (int u = 0; u < 4; u++)
                #pragma unroll
                for (int j = 0; j < 4; j++) acc[u][j] += a_[u] * b_[j];
        }
        __syncthreads();
    }
    #pragma unroll
    for (int u = 0; u < 4; u++) {
        int m = m0 + ty * 4 + u;
        float bv = bias[m];
        float4 o = make_float4(acc[u][0] + bv, acc[u][1] + bv,
                               acc[u][2] + bv, acc[u][3] + bv);
        *(float4*)&Yb[(size_t)m * 16384 + tx * 4] = o;
    }
}

// ---------------- transpose NCHW -> [b][p][c] fp16 ----------------
__global__ __launch_bounds__(256) void transpose_x(const float* __restrict__ X,
                                                   uint32_t* __restrict__ Xt)
{
    __shared__ float t[32][65];
    int p0 = blockIdx.x * 64, c0 = blockIdx.y * 32, b = blockIdx.z;
    const float* src = X + ((size_t)b * 384 + c0) * 16384 + p0;
    for (int i = threadIdx.x; i < 2048; i += 256) {
        int c = i >> 6, p = i & 63;
        t[c][p] = src[(size_t)c * 16384 + p];
    }
    __syncthreads();
    uint32_t* dst = Xt + (size_t)b * 3145728 + (size_t)p0 * 192 + (c0 >> 1);
    for (int i = threadIdx.x; i < 1024; i += 256) {
        int p = i >> 4, cp = i & 15;
        __half2 h = __floats2half2_rn(t[cp * 2][p], t[cp * 2 + 1][p]);
        dst[(size_t)p * 192 + cp] = *(uint32_t*)&h;
    }
}

// ---------------- 3x3 conv: mma.sync fp16 m16n8k16, ldmatrix B loads ----------------
// Grid (128 y, 3 octile128, 2 b); 256 thr = 8 warps.
// Warp tile: 32 oc x 64 x. kstep = kx*72 + ky*24 + cb*2 + ks (216 total of K=16).
// A frags double-buffered in regs (prefetch 1 chunk ahead); B frags via ldmatrix.x4.
__global__ __launch_bounds__(256, 2) void conv3x3_mma(
    const uint32_t* __restrict__ Xt, const float* __restrict__ bias,
    float* __restrict__ Y)
{
    __shared__ __align__(16) uint32_t in_s[130 * 20];  // [x+1][c half2], stride 20
    int tid = threadIdx.x, wid = tid >> 5, lane = tid & 31;
    int y0 = blockIdx.x, by = blockIdx.y, b = blockIdx.z;
    int oct0 = by * 8 + (wid >> 1) * 2;      // warp's first octile (16 oc)
    int xw = (wid & 1) * 64;                 // warp's x offset

    const uint4* Wh4 = (const uint4*)g_Wh;
    const uint4* pW0 = Wh4 + (size_t)(oct0 * 216) * 32 + lane;
    const uint4* pW1 = pW0 + (size_t)216 * 32;

    // ldmatrix row base: row x = (lane&7) + ((lane>>4)<<3), matrix-half m = (lane>>3)&1
    uint32_t bbase = smem_u32(in_s)
                   + (uint32_t)(((lane & 7) + ((lane >> 4) << 3)) * 80)
                   + (uint32_t)(((lane >> 3) & 1) * 16)
                   + (uint32_t)(xw * 80);

    float acc[2][8][4] = {};
    uint4 Abuf[2][2];   // [buf][octile]

    // preload kstep 0 into buf 0
    Abuf[0][0] = pW0[0];
    Abuf[0][1] = pW1[0];

    for (int ky = 0; ky < 3; ky++) {
        int yin = y0 - 1 + ky;
        bool okrow = ((unsigned)yin < 128u);
        const uint4* Xrow = (const uint4*)(Xt + ((size_t)b * 16384 + (size_t)yin * 128) * 192);
        for (int cb = 0; cb < 12; cb++) {
            __syncthreads();
            // stage 130 x-rows x 32 c halves; [x][c] half2, stride 20 u32
            for (int idx = tid; idx < 520; idx += 256) {
                int row = idx >> 2, q = idx & 3;
                int x = row - 1;
                uint4 v = make_uint4(0u, 0u, 0u, 0u);
                if (okrow && (unsigned)x < 128u)
                    v = Xrow[(size_t)x * 48 + cb * 4 + q];
                *(uint4*)&in_s[row * 20 + q * 4] = v;
            }
            __syncthreads();
            #pragma unroll
            for (int kx = 0; kx < 3; kx++) {
                #pragma unroll
                for (int ks = 0; ks < 2; ks++) {
                    const int cidx = kx * 2 + ks;     // chunk 0..5 (const)
                    const int pb = cidx & 1;          // current buffer (const)
                    // ---- prefetch next chunk's A frags ----
                    int nstep; bool valid = true;
                    if (cidx < 5) {
                        int nx = (cidx + 1) >> 1, nk = (cidx + 1) & 1;
                        nstep = nx * 72 + ky * 24 + cb * 2 + nk;
                    } else {
                        int cbn = cb + 1, kyn = ky;
                        if (cbn == 12) { cbn = 0; kyn++; }
                        valid = kyn < 3;
                        nstep = kyn * 24 + cbn * 2;
                    }
                    if (valid) {
                        Abuf[pb ^ 1][0] = pW0[(size_t)nstep * 32];
                        Abuf[pb ^ 1][1] = pW1[(size_t)nstep * 32];
                    }
                    // ---- B fragments: 4 x ldmatrix.x4 covering 8 n-tiles ----
                    uint32_t Bf[4][4];
                    uint32_t badd = bbase + (uint32_t)(kx * 80 + ks * 32);
                    #pragma unroll
                    for (int g = 0; g < 4; g++)
                        ldsm4(Bf[g], badd + (uint32_t)(g * 1280));  // 16 rows * 80B
                    // ---- consume: 16 HMMA ----
                    uint4 A0v = Abuf[pb][0];
                    uint4 A1v = Abuf[pb][1];
                    uint32_t a0[4] = {A0v.x, A0v.y, A0v.z, A0v.w};
                    uint32_t a1[4] = {A1v.x, A1v.y, A1v.z, A1v.w};
                    #pragma unroll
                    for (int g = 0; g < 4; g++) {
                        #pragma unroll
                        for (int sub = 0; sub < 2; sub++) {
                            int n = g * 2 + sub;
                            uint32_t b0 = Bf[g][sub * 2];
                            uint32_t b1 = Bf[g][sub * 2 + 1];
                            mma16(acc[0][n], a0, b0, b1);
                            mma16(acc[1][n], a1, b0, b1);
                        }
                    }
                }
            }
        }
    }

    // epilogue: C frag rows = oc, cols = x
    float* Yb = Y + (size_t)b * 384 * 16384 + (size_t)y0 * 128;
    #pragma unroll
    for (int m = 0; m < 2; m++) {
        int ocb = (oct0 + m) * 16 + (lane >> 2);
        float bv0 = bias[ocb];
        float bv1 = bias[ocb + 8];
        #pragma unroll
        for (int n = 0; n < 8; n++) {
            int x = xw + n * 8 + (lane & 3) * 2;
            float2 v0 = make_float2(acc[m][n][0] + bv0, acc[m][n][1] + bv0);
            float2 v1 = make_float2(acc[m][n][2] + bv1, acc[m][n][3] + bv1);
            *(float2*)&Yb[(size_t)ocb * 16384 + x] = v0;
            *(float2*)&Yb[(size_t)(ocb + 8) * 16384 + x] = v1;
        }
    }
}

// ---------------- L2 norms ----------------
__global__ void norm_kernel(const float* __restrict__ Q2, float* __restrict__ rn)
{
    int b = blockIdx.x >> 8, ch = blockIdx.x & 255;
    const float* p = Q2 + ((size_t)b * 384 + ch) * 16384;
    float s = 0.f;
    for (int i = threadIdx.x; i < 16384; i += 256) { float v = p[i]; s += v * v; }
    __shared__ float red[8];
    #pragma unroll
    for (int o = 16; o; o >>= 1) s += __shfl_xor_sync(~0u, s, o);
    if ((threadIdx.x & 31) == 0) red[threadIdx.x >> 5] = s;
    __syncthreads();
    if (threadIdx.x < 8) {
        s = red[threadIdx.x];
        #pragma unroll
        for (int o = 4; o; o >>= 1) s += __shfl_xor_sync(0xffu, s, o);
        if (threadIdx.x == 0) rn[blockIdx.x] = 1.f / fmaxf(sqrtf(s), 1e-12f);
    }
}

// ---------------- QK^T partials ----------------
__global__ __launch_bounds__(256) void attn_qk(const float* __restrict__ Q2)
{
    int slice = blockIdx.x & 31, h = (blockIdx.x >> 5) & 3, b = blockIdx.x >> 7;
    __shared__ float qs[32 * 129], ks[32 * 129];
    int t = threadIdx.x;
    int c0 = t >> 3, d0 = (t & 7) << 2;
    const float* qp = Q2 + ((size_t)b * 384 + h * 32) * 16384;
    const float* kp = Q2 + ((size_t)b * 384 + 128 + h * 32) * 16384;
    float acc[4] = {};
    int sbase = slice * 512;
    for (int ch = 0; ch < 4; ch++) {
        int s0 = sbase + ch * 128;
        for (int i = t; i < 4096; i += 256) {
            int c = i >> 7, s = i & 127;
            qs[c * 129 + s] = qp[(size_t)c * 16384 + s0 + s];
            ks[c * 129 + s] = kp[(size_t)c * 16384 + s0 + s];
        }
        __syncthreads();
        #pragma unroll 4
        for (int s = 0; s < 128; s++) {
            float qv = qs[c0 * 129 + s];
            #pragma unroll
            for (int j = 0; j < 4; j++) acc[j] += qv * ks[(d0 + j) * 129 + s];
        }
        __syncthreads();
    }
    float* pp = g_part + (((size_t)(b * 4 + h) * 32 + slice) * 1024) + c0 * 32 + d0;
    #pragma unroll
    for (int j = 0; j < 4; j++) pp[j] = acc[j];
}

// ---------------- softmax: one block per (b,h), warp per attn row ----------------
__global__ __launch_bounds__(1024) void softmax_kernel(
    const float* __restrict__ rn, const float* __restrict__ temp)
{
    int bh = blockIdx.x;             // b*4 + h
    int b = bh >> 2, h = bh & 3;
    int c = threadIdx.x >> 5, d = threadIdx.x & 31;
    const float* base = g_part + (size_t)bh * 32768 + c * 32 + d;
    float v = 0.f;
    #pragma unroll 8
    for (int sl = 0; sl < 32; sl++) v += base[(size_t)sl * 1024];
    float rq = rn[b * 256 + h * 32 + c];
    float rk = rn[b * 256 + 128 + h * 32 + d];
    v = v * rq * rk * temp[h];
    float mx = v;
    #pragma unroll
    for (int o = 16; o; o >>= 1) mx = fmaxf(mx, __shfl_xor_sync(~0u, mx, o));
    float e = __expf(v - mx);
    float sum = e;
    #pragma unroll
    for (int o = 16; o; o >>= 1) sum += __shfl_xor_sync(~0u, sum, o);
    g_attn[(size_t)bh * 1024 + c * 32 + d] = e / sum;
}

// ---------------- out = attn @ v ----------------
__global__ __launch_bounds__(256) void attn_v(const float* __restrict__ Q2,
                                              float* __restrict__ Aout)
{
    int st = blockIdx.x & 63, h = (blockIdx.x >> 6) & 3, b = blockIdx.x >> 8;
    __shared__ float A[1024];
    int t = threadIdx.x;
    for (int i = t; i < 1024; i += 256) A[i] = g_attn[(size_t)(b * 4 + h) * 1024 + i];
    __syncthreads();
    int s = st * 256 + t;
    const float* vp = Q2 + ((size_t)b * 384 + 256 + h * 32) * 16384 + s;
    float vr[32];
    #pragma unroll
    for (int d = 0; d < 32; d++) vr[d] = vp[(size_t)d * 16384];
    float* op = Aout + ((size_t)b * 128 + h * 32) * 16384 + s;
    #pragma unroll
    for (int c = 0; c < 32; c++) {
        float sum = 0.f;
        #pragma unroll
        for (int d = 0; d < 32; d++) sum += A[c * 32 + d] * vr[d];
        op[(size_t)c * 16384] = sum;
    }
}

// ---------------- launch ----------------
extern "C" void kernel_launch(void* const* d_in, const int* in_sizes, int n_in,
                              void* d_out, int out_size)
{
    const float* x    = (const float*)d_in[0];
    const float* qr   = (const float*)d_in[1];
    const float* qi   = (const float*)d_in[2];
    const float* qj   = (const float*)d_in[3];
    const float* qk   = (const float*)d_in[4];
    const float* qkvb = (const float*)d_in[5];
    const float* dr   = (const float*)d_in[6];
    const float* di   = (const float*)d_in[7];
    const float* dj   = (const float*)d_in[8];
    const float* dk   = (const float*)d_in[9];
    const float* dwb  = (const float*)d_in[10];
    const float* pr   = (const float*)d_in[11];
    const float* pi   = (const float*)d_in[12];
    const float* pj   = (const float*)d_in[13];
    const float* pk   = (const float*)d_in[14];
    const float* pob  = (const float*)d_in[15];
    const float* temp = (const float*)d_in[16];
    float* out = (float*)d_out;

    float *pQ1, *pQ2, *pRn, *pAout;
    uint32_t* pXt;
    cudaGetSymbolAddress((void**)&pQ1, g_qkv1);
    cudaGetSymbolAddress((void**)&pQ2, g_qkv2);
    cudaGetSymbolAddress((void**)&pRn, g_rnorm);
    cudaGetSymbolAddress((void**)&pAout, g_aout);
    cudaGetSymbolAddress((void**)&pXt, g_xth);

    build_weights<<<512, 256>>>(qr, qi, qj, qk, dr, di, dj, dk, pr, pi, pj, pk);
    gemm1x1<<<dim3(512, 6), 256>>>(0, x, qkvb, pQ1, 384, 128);
    transpose_x<<<dim3(256, 12, 2), 256>>>(pQ1, pXt);
    conv3x3_mma<<<dim3(128, 3, 2), 256>>>(pXt, dwb, pQ2);
    norm_kernel<<<512, 256>>>(pQ2, pRn);
    attn_qk<<<256, 256>>>(pQ2);
    softmax_kernel<<<8, 1024>>>(pRn, temp);
    attn_v<<<512, 256>>>(pQ2, pAout);
    gemm1x1<<<dim3(512, 2), 256>>>(1, pAout, pob, out, 128, 128);
}

// round 14
// speedup vs baseline: 1.7494x; 1.7494x over previous
#include <cuda_runtime.h>
#include <cuda_fp16.h>
#include <stdint.h>

// ---------------- device scratch ----------------
__device__ uint32_t g_W1h[24 * 8 * 128];      // qkv 1x1 weights, fp16 A-frag (half2)
__device__ uint32_t g_Wh[24 * 216 * 128];     // dw 3x3 weights, fp16 A-frag (half2)
__device__ float    g_Wp[128 * 128];          // po 1x1 weights, transposed [c][o]
__device__ uint32_t g_xh[2 * 16384 * 64];     // input x as [b][p][c/2] half2
__device__ uint32_t g_xth[2 * 16384 * 192];   // qkv1 as [b][p][c/2] half2 (conv input)
__device__ float    g_qkv2[2 * 384 * 16384];  // after 3x3 conv (NCHW)
__device__ float    g_rnorm[2 * 256];
__device__ float    g_part[2 * 4 * 32 * 1024];
__device__ float    g_attn[2 * 4 * 32 * 32];
__device__ float    g_aout[2 * 128 * 16384];

__constant__ int   c_src[16] = {0,1,2,3, 1,0,3,2, 2,3,0,1, 3,2,1,0};
__constant__ float c_sgn[16] = {1,-1,-1,-1, 1,1,-1,1, 1,1,1,-1, 1,-1,1,1};

static __device__ __forceinline__ void mma16(float* d, const uint32_t* a,
                                             uint32_t b0, uint32_t b1) {
    asm volatile(
        "mma.sync.aligned.m16n8k16.row.col.f32.f16.f16.f32 "
        "{%0,%1,%2,%3}, {%4,%5,%6,%7}, {%8,%9}, {%0,%1,%2,%3};"
        : "+f"(d[0]), "+f"(d[1]), "+f"(d[2]), "+f"(d[3])
        : "r"(a[0]), "r"(a[1]), "r"(a[2]), "r"(a[3]), "r"(b0), "r"(b1));
}

// ---------------- build quaternion weight matrices ----------------
// frag layouts: idx = ((octile*NK + kstep)*32 + lane)*4 + j, halves e=0,1
//   oc = octile*16 + (lane>>2) + (j&1)*8
//   kk = kstep*16 + (lane&3)*2 + e + (j>>1)*8
__global__ void build_weights(
    const float* __restrict__ qr, const float* __restrict__ qi,
    const float* __restrict__ qj, const float* __restrict__ qk,
    const float* __restrict__ dr, const float* __restrict__ di,
    const float* __restrict__ dj, const float* __restrict__ dk,
    const float* __restrict__ pr, const float* __restrict__ pi,
    const float* __restrict__ pj, const float* __restrict__ pk)
{
    const float* qb[4] = {qr, qi, qj, qk};
    const float* db[4] = {dr, di, dj, dk};
    const float* pb[4] = {pr, pi, pj, pk};
    const int N1 = 24 * 8 * 128;       // qkv frag half2 count
    const int NH = 24 * 216 * 128;     // dw frag half2 count
    const int NP = 128 * 128;
    int total = N1 + NH + NP;
    for (int i = blockIdx.x * blockDim.x + threadIdx.x; i < total;
         i += gridDim.x * blockDim.x) {
        if (i < N1) {
            int j = i & 3, lane = (i >> 2) & 31;
            int rest = i >> 7;
            int kstep = rest % 8, octile = rest / 8;
            int oc = octile * 16 + (lane >> 2) + (j & 1) * 8;
            float w[2];
            #pragma unroll
            for (int e = 0; e < 2; e++) {
                int c = kstep * 16 + (lane & 3) * 2 + e + ((j >> 1) << 3);
                int br = oc / 96, oo = oc % 96, bc = c / 32, cc = c % 32;
                int hi = br * 4 + bc;
                w[e] = c_sgn[hi] * qb[c_src[hi]][oo * 32 + cc];
            }
            __half2 h = __floats2half2_rn(w[0], w[1]);
            g_W1h[i] = *(uint32_t*)&h;
        } else if (i < N1 + NH) {
            int idx = i - N1;
            int j = idx & 3, lane = (idx >> 2) & 31;
            int rest = idx >> 7;
            int kstep = rest % 216, octile = rest / 216;
            int oc = octile * 16 + (lane >> 2) + (j & 1) * 8;
            float w[2];
            #pragma unroll
            for (int e = 0; e < 2; e++) {
                int kk = kstep * 16 + (lane & 3) * 2 + e + ((j >> 1) << 3);
                int kx = kk / 1152, rem = kk % 1152;
                int ky = rem / 384, c = rem % 384;
                int br = oc / 96, oo = oc % 96, bc = c / 96, cc = c % 96;
                int hi = br * 4 + bc;
                w[e] = c_sgn[hi] * db[c_src[hi]][(oo * 96 + cc) * 9 + ky * 3 + kx];
            }
            __half2 h = __floats2half2_rn(w[0], w[1]);
            g_Wh[idx] = *(uint32_t*)&h;
        } else {
            int idx = i - N1 - NH;
            int o = idx % 128, c = idx / 128;
            int br = o / 32, oo = o % 32, bc = c / 32, cc = c % 32;
            int hi = br * 4 + bc;
            g_Wp[idx] = c_sgn[hi] * pb[c_src[hi]][oo * 32 + cc];
        }
    }
}

// ---------------- transpose input x: NCHW fp32 -> [b][p][c/2] half2 ----------------
__global__ __launch_bounds__(256) void transpose_xin(const float* __restrict__ X,
                                                     uint32_t* __restrict__ Xh)
{
    __shared__ float t[32][65];
    int p0 = blockIdx.x * 64, c0 = blockIdx.y * 32, b = blockIdx.z;
    const float* src = X + ((size_t)b * 128 + c0) * 16384 + p0;
    for (int i = threadIdx.x; i < 2048; i += 256) {
        int c = i >> 6, p = i & 63;
        t[c][p] = src[(size_t)c * 16384 + p];
    }
    __syncthreads();
    uint32_t* dst = Xh + (size_t)b * 1048576 + (size_t)p0 * 64 + (c0 >> 1);
    for (int i = threadIdx.x; i < 1024; i += 256) {
        int p = i >> 4, cp = i & 15;
        __half2 h = __floats2half2_rn(t[cp * 2][p], t[cp * 2 + 1][p]);
        dst[(size_t)p * 64 + cp] = *(uint32_t*)&h;
    }
}

// ---------------- qkv 1x1: fp16 mma GEMM, writes transposed fp16 output ----------------
// Grid (128 pblock, 3 mblock, 2 b); 256 thr = 8 warps; warp tile 32m x 64p; K=128.
__global__ __launch_bounds__(256, 2) void gemm_qkv_mma(
    const uint32_t* __restrict__ Xh, const float* __restrict__ bias,
    uint32_t* __restrict__ Xt)
{
    __shared__ __align__(16) char gsm[128 * 130 * 2];   // union: in_s / ep
    uint32_t* in_s = (uint32_t*)gsm;                    // [128p][stride 20 u32]
    __half* ep = (__half*)gsm;                          // [128p][130]
    int tid = threadIdx.x, wid = tid >> 5, lane = tid & 31;
    int pblk = blockIdx.x, mb = blockIdx.y, b = blockIdx.z;
    int oct0 = mb * 8 + (wid >> 1) * 2;
    int xw = (wid & 1) * 64;

    const uint4* W4 = (const uint4*)g_W1h;
    const uint4* pW0 = W4 + (size_t)(oct0 * 8) * 32 + lane;
    const uint4* pW1 = pW0 + (size_t)8 * 32;

    float acc[2][8][4] = {};
    uint4 Abuf[2][2];
    Abuf[0][0] = pW0[0];
    Abuf[0][1] = pW1[0];

    const uint4* Xrow = (const uint4*)(Xh + ((size_t)b * 16384 + (size_t)pblk * 128) * 64);
    for (int cb = 0; cb < 4; cb++) {
        __syncthreads();
        // stage 128 p-rows x 32 c halves = 16 u32/row, stride 20
        for (int idx = tid; idx < 512; idx += 256) {
            int row = idx >> 2, q = idx & 3;
            uint4 v = Xrow[(size_t)row * 16 + cb * 4 + q];
            *(uint4*)&in_s[row * 20 + q * 4] = v;
        }
        __syncthreads();
        #pragma unroll
        for (int ks = 0; ks < 2; ks++) {
            const int cidx = cb * 2 + ks;
            const int pb = cidx & 1;
            if (cidx < 7) {
                int nstep = cidx + 1;
                Abuf[pb ^ 1][0] = pW0[(size_t)nstep * 32];
                Abuf[pb ^ 1][1] = pW1[(size_t)nstep * 32];
            }
            uint4 A0v = Abuf[pb][0];
            uint4 A1v = Abuf[pb][1];
            uint32_t a0[4] = {A0v.x, A0v.y, A0v.z, A0v.w};
            uint32_t a1[4] = {A1v.x, A1v.y, A1v.z, A1v.w};
            int cbase = ks * 8 + (lane & 3);
            int xbase = xw + (lane >> 2);
            #pragma unroll
            for (int n = 0; n < 8; n++) {
                int xr = xbase + n * 8;
                uint32_t b0 = in_s[xr * 20 + cbase];
                uint32_t b1 = in_s[xr * 20 + cbase + 4];
                mma16(acc[0][n], a0, b0, b1);
                mma16(acc[1][n], a1, b0, b1);
            }
        }
    }

    // epilogue: transpose through smem to [p][c] half, then coalesced u32 stores
    __syncthreads();
    #pragma unroll
    for (int m = 0; m < 2; m++) {
        int cl = ((wid >> 1) * 2 + m) * 16 + (lane >> 2);   // local c 0..127
        float bv0 = bias[mb * 128 + cl];
        float bv1 = bias[mb * 128 + cl + 8];
        #pragma unroll
        for (int n = 0; n < 8; n++) {
            int p = xw + n * 8 + (lane & 3) * 2;
            ep[p * 130 + cl]           = __float2half(acc[m][n][0] + bv0);
            ep[(p + 1) * 130 + cl]     = __float2half(acc[m][n][1] + bv0);
            ep[p * 130 + cl + 8]       = __float2half(acc[m][n][2] + bv1);
            ep[(p + 1) * 130 + cl + 8] = __float2half(acc[m][n][3] + bv1);
        }
    }
    __syncthreads();
    uint32_t* dst = Xt + ((size_t)b * 16384 + (size_t)pblk * 128) * 192 + mb * 64;
    for (int idx = tid; idx < 8192; idx += 256) {
        int p = idx >> 6, cw = idx & 63;
        uint32_t v = *(const uint32_t*)&ep[p * 130 + cw * 2];
        dst[(size_t)p * 192 + cw] = v;
    }
}

// ---------------- 3x3 conv: mma.sync fp16 m16n8k16 implicit GEMM (R11 proven) ----------------
__global__ __launch_bounds__(256, 2) void conv3x3_mma(
    const uint32_t* __restrict__ Xt, const float* __restrict__ bias,
    float* __restrict__ Y)
{
    __shared__ __align__(16) uint32_t in_s[130 * 20];  // [x+1][c half2], stride 20
    int tid = threadIdx.x, wid = tid >> 5, lane = tid & 31;
    int y0 = blockIdx.x, by = blockIdx.y, b = blockIdx.z;
    int oct0 = by * 8 + (wid >> 1) * 2;
    int xw = (wid & 1) * 64;

    const uint4* Wh4 = (const uint4*)g_Wh;
    const uint4* pW0 = Wh4 + (size_t)(oct0 * 216) * 32 + lane;
    const uint4* pW1 = pW0 + (size_t)216 * 32;

    float acc[2][8][4] = {};
    uint4 Abuf[2][2];
    Abuf[0][0] = pW0[0];
    Abuf[0][1] = pW1[0];

    for (int ky = 0; ky < 3; ky++) {
        int yin = y0 - 1 + ky;
        bool okrow = ((unsigned)yin < 128u);
        const uint4* Xrow = (const uint4*)(Xt + ((size_t)b * 16384 + (size_t)yin * 128) * 192);
        for (int cb = 0; cb < 12; cb++) {
            __syncthreads();
            for (int idx = tid; idx < 520; idx += 256) {
                int row = idx >> 2, q = idx & 3;
                int x = row - 1;
                uint4 v = make_uint4(0u, 0u, 0u, 0u);
                if (okrow && (unsigned)x < 128u)
                    v = Xrow[(size_t)x * 48 + cb * 4 + q];
                *(uint4*)&in_s[row * 20 + q * 4] = v;
            }
            __syncthreads();
            #pragma unroll
            for (int kx = 0; kx < 3; kx++) {
                #pragma unroll
                for (int ks = 0; ks < 2; ks++) {
                    const int cidx = kx * 2 + ks;
                    const int pb = cidx & 1;
                    int nstep; bool valid = true;
                    if (cidx < 5) {
                        int nx = (cidx + 1) >> 1, nk = (cidx + 1) & 1;
                        nstep = nx * 72 + ky * 24 + cb * 2 + nk;
                    } else {
                        int cbn = cb + 1, kyn = ky;
                        if (cbn == 12) { cbn = 0; kyn++; }
                        valid = kyn < 3;
                        nstep = kyn * 24 + cbn * 2;
                    }
                    if (valid) {
                        Abuf[pb ^ 1][0] = pW0[(size_t)nstep * 32];
                        Abuf[pb ^ 1][1] = pW1[(size_t)nstep * 32];
                    }
                    uint4 A0v = Abuf[pb][0];
                    uint4 A1v = Abuf[pb][1];
                    uint32_t a0[4] = {A0v.x, A0v.y, A0v.z, A0v.w};
                    uint32_t a1[4] = {A1v.x, A1v.y, A1v.z, A1v.w};
                    int cbase = ks * 8 + (lane & 3);
                    int xbase = xw + (lane >> 2) + kx;
                    #pragma unroll
                    for (int n = 0; n < 8; n++) {
                        int xr = xbase + n * 8;
                        uint32_t b0 = in_s[xr * 20 + cbase];
                        uint32_t b1 = in_s[xr * 20 + cbase + 4];
                        mma16(acc[0][n], a0, b0, b1);
                        mma16(acc[1][n], a1, b0, b1);
                    }
                }
            }
        }
    }

    float* Yb = Y + (size_t)b * 384 * 16384 + (size_t)y0 * 128;
    #pragma unroll
    for (int m = 0; m < 2; m++) {
        int ocb = (oct0 + m) * 16 + (lane >> 2);
        float bv0 = bias[ocb];
        float bv1 = bias[ocb + 8];
        #pragma unroll
        for (int n = 0; n < 8; n++) {
            int x = xw + n * 8 + (lane & 3) * 2;
            float2 v0 = make_float2(acc[m][n][0] + bv0, acc[m][n][1] + bv0);
            float2 v1 = make_float2(acc[m][n][2] + bv1, acc[m][n][3] + bv1);
            *(float2*)&Yb[(size_t)ocb * 16384 + x] = v0;
            *(float2*)&Yb[(size_t)(ocb + 8) * 16384 + x] = v1;
        }
    }
}

// ---------------- po 1x1 conv = tiled SGEMM (fp32) ----------------
__global__ __launch_bounds__(256) void gemm_po(
    const float* __restrict__ X, const float* __restrict__ bias,
    float* __restrict__ Y)
{
    __shared__ __align__(16) float Ws[16][64];
    __shared__ __align__(16) float Xs[16][64];
    const int M = 128, K = 128;
    int m0 = blockIdx.y * 64;
    int n  = blockIdx.x * 64;
    int b  = n >> 14; int p0 = n & 16383;
    const float* Xb = X + (size_t)b * K * 16384 + p0;
    float* Yb = Y + (size_t)b * M * 16384 + p0;
    int t = threadIdx.x;
    int tx = t & 15, ty = t >> 4;
    float acc[4][4] = {};
    for (int k0 = 0; k0 < K; k0 += 16) {
        #pragma unroll
        for (int i = t; i < 1024; i += 256) {
            int mm = i & 63, kk = i >> 6;
            Ws[kk][mm] = g_Wp[(size_t)(k0 + kk) * M + m0 + mm];
            Xs[kk][mm] = Xb[(size_t)(k0 + kk) * 16384 + mm];
        }
        __syncthreads();
        #pragma unroll
        for (int kk = 0; kk < 16; kk++) {
            float4 a4 = *(const float4*)&Ws[kk][ty * 4];
            float4 b4 = *(const float4*)&Xs[kk][tx * 4];
            float a_[4] = {a4.x, a4.y, a4.z, a4.w};
            float b_[4] = {b4.x, b4.y, b4.z, b4.w};
            #pragma unroll
            for (int u = 0; u < 4; u++)
                #pragma unroll
                for (int j = 0; j < 4; j++) acc[u][j] += a_[u] * b_[j];
        }
        __syncthreads();
    }
    #pragma unroll
    for (int u = 0; u < 4; u++) {
        int m = m0 + ty * 4 + u;
        float bv = bias[m];
        float4 o = make_float4(acc[u][0] + bv, acc[u][1] + bv,
                               acc[u][2] + bv, acc[u][3] + bv);
        *(float4*)&Yb[(size_t)m * 16384 + tx * 4] = o;
    }
}

// ---------------- L2 norms ----------------
__global__ void norm_kernel(const float* __restrict__ Q2, float* __restrict__ rn)
{
    int b = blockIdx.x >> 8, ch = blockIdx.x & 255;
    const float* p = Q2 + ((size_t)b * 384 + ch) * 16384;
    float s = 0.f;
    for (int i = threadIdx.x; i < 16384; i += 256) { float v = p[i]; s += v * v; }
    __shared__ float red[8];
    #pragma unroll
    for (int o = 16; o; o >>= 1) s += __shfl_xor_sync(~0u, s, o);
    if ((threadIdx.x & 31) == 0) red[threadIdx.x >> 5] = s;
    __syncthreads();
    if (threadIdx.x < 8) {
        s = red[threadIdx.x];
        #pragma unroll
        for (int o = 4; o; o >>= 1) s += __shfl_xor_sync(0xffu, s, o);
        if (threadIdx.x == 0) rn[blockIdx.x] = 1.f / fmaxf(sqrtf(s), 1e-12f);
    }
}

// ---------------- QK^T partials ----------------
__global__ __launch_bounds__(256) void attn_qk(const float* __restrict__ Q2)
{
    int slice = blockIdx.x & 31, h = (blockIdx.x >> 5) & 3, b = blockIdx.x >> 7;
    __shared__ float qs[32 * 129], ks[32 * 129];
    int t = threadIdx.x;
    int c0 = t >> 3, d0 = (t & 7) << 2;
    const float* qp = Q2 + ((size_t)b * 384 + h * 32) * 16384;
    const float* kp = Q2 + ((size_t)b * 384 + 128 + h * 32) * 16384;
    float acc[4] = {};
    int sbase = slice * 512;
    for (int ch = 0; ch < 4; ch++) {
        int s0 = sbase + ch * 128;
        for (int i = t; i < 4096; i += 256) {
            int c = i >> 7, s = i & 127;
            qs[c * 129 + s] = qp[(size_t)c * 16384 + s0 + s];
            ks[c * 129 + s] = kp[(size_t)c * 16384 + s0 + s];
        }
        __syncthreads();
        #pragma unroll 4
        for (int s = 0; s < 128; s++) {
            float qv = qs[c0 * 129 + s];
            #pragma unroll
            for (int j = 0; j < 4; j++) acc[j] += qv * ks[(d0 + j) * 129 + s];
        }
        __syncthreads();
    }
    float* pp = g_part + (((size_t)(b * 4 + h) * 32 + slice) * 1024) + c0 * 32 + d0;
    #pragma unroll
    for (int j = 0; j < 4; j++) pp[j] = acc[j];
}

// ---------------- softmax: one block per (b,h), warp per attn row ----------------
__global__ __launch_bounds__(1024) void softmax_kernel(
    const float* __restrict__ rn, const float* __restrict__ temp)
{
    int bh = blockIdx.x;
    int b = bh >> 2, h = bh & 3;
    int c = threadIdx.x >> 5, d = threadIdx.x & 31;
    const float* base = g_part + (size_t)bh * 32768 + c * 32 + d;
    float v = 0.f;
    #pragma unroll 8
    for (int sl = 0; sl < 32; sl++) v += base[(size_t)sl * 1024];
    float rq = rn[b * 256 + h * 32 + c];
    float rk = rn[b * 256 + 128 + h * 32 + d];
    v = v * rq * rk * temp[h];
    float mx = v;
    #pragma unroll
    for (int o = 16; o; o >>= 1) mx = fmaxf(mx, __shfl_xor_sync(~0u, mx, o));
    float e = __expf(v - mx);
    float sum = e;
    #pragma unroll
    for (int o = 16; o; o >>= 1) sum += __shfl_xor_sync(~0u, sum, o);
    g_attn[(size_t)bh * 1024 + c * 32 + d] = e / sum;
}

// ---------------- out = attn @ v ----------------
__global__ __launch_bounds__(256) void attn_v(const float* __restrict__ Q2,
                                              float* __restrict__ Aout)
{
    int st = blockIdx.x & 63, h = (blockIdx.x >> 6) & 3, b = blockIdx.x >> 8;
    __shared__ float A[1024];
    int t = threadIdx.x;
    for (int i = t; i < 1024; i += 256) A[i] = g_attn[(size_t)(b * 4 + h) * 1024 + i];
    __syncthreads();
    int s = st * 256 + t;
    const float* vp = Q2 + ((size_t)b * 384 + 256 + h * 32) * 16384 + s;
    float vr[32];
    #pragma unroll
    for (int d = 0; d < 32; d++) vr[d] = vp[(size_t)d * 16384];
    float* op = Aout + ((size_t)b * 128 + h * 32) * 16384 + s;
    #pragma unroll
    for (int c = 0; c < 32; c++) {
        float sum = 0.f;
        #pragma unroll
        for (int d = 0; d < 32; d++) sum += A[c * 32 + d] * vr[d];
        op[(size_t)c * 16384] = sum;
    }
}

// ---------------- launch ----------------
extern "C" void kernel_launch(void* const* d_in, const int* in_sizes, int n_in,
                              void* d_out, int out_size)
{
    const float* x    = (const float*)d_in[0];
    const float* qr   = (const float*)d_in[1];
    const float* qi   = (const float*)d_in[2];
    const float* qj   = (const float*)d_in[3];
    const float* qk   = (const float*)d_in[4];
    const float* qkvb = (const float*)d_in[5];
    const float* dr   = (const float*)d_in[6];
    const float* di   = (const float*)d_in[7];
    const float* dj   = (const float*)d_in[8];
    const float* dk   = (const float*)d_in[9];
    const float* dwb  = (const float*)d_in[10];
    const float* pr   = (const float*)d_in[11];
    const float* pi   = (const float*)d_in[12];
    const float* pj   = (const float*)d_in[13];
    const float* pk   = (const float*)d_in[14];
    const float* pob  = (const float*)d_in[15];
    const float* temp = (const float*)d_in[16];
    float* out = (float*)d_out;

    float *pQ2, *pRn, *pAout;
    uint32_t *pXh, *pXt;
    cudaGetSymbolAddress((void**)&pQ2, g_qkv2);
    cudaGetSymbolAddress((void**)&pRn, g_rnorm);
    cudaGetSymbolAddress((void**)&pAout, g_aout);
    cudaGetSymbolAddress((void**)&pXh, g_xh);
    cudaGetSymbolAddress((void**)&pXt, g_xth);

    build_weights<<<512, 256>>>(qr, qi, qj, qk, dr, di, dj, dk, pr, pi, pj, pk);
    transpose_xin<<<dim3(256, 4, 2), 256>>>(x, pXh);
    gemm_qkv_mma<<<dim3(128, 3, 2), 256>>>(pXh, qkvb, pXt);
    conv3x3_mma<<<dim3(128, 3, 2), 256>>>(pXt, dwb, pQ2);
    norm_kernel<<<512, 256>>>(pQ2, pRn);
    attn_qk<<<256, 256>>>(pQ2);
    softmax_kernel<<<8, 1024>>>(pRn, temp);
    attn_v<<<512, 256>>>(pQ2, pAout);
    gemm_po<<<dim3(512, 2), 256>>>(pAout, pob, out);
}

// round 16
// speedup vs baseline: 1.9514x; 1.1154x over previous
#include <cuda_runtime.h>
#include <cuda_fp16.h>
#include <stdint.h>

// ---------------- device scratch ----------------
__device__ uint32_t g_W1h[24 * 8 * 128];      // qkv 1x1 weights, fp16 A-frag (half2)
__device__ uint32_t g_Wh[24 * 216 * 128];     // dw 3x3 weights, fp16 A-frag (half2)
__device__ uint32_t g_Wph[8 * 8 * 128];       // po 1x1 weights, fp16 A-frag (half2)
__device__ uint32_t g_xh[2 * 16384 * 64];     // input x as [b][p][c/2] half2
__device__ uint32_t g_xth[2 * 16384 * 192];   // qkv1 as [b][p][c/2] half2 (conv input)
__device__ float    g_qkv2[2 * 384 * 16384];  // after 3x3 conv (NCHW)
__device__ float    g_rnorm[2 * 256];
__device__ float    g_part[2 * 4 * 32 * 1024];
__device__ float    g_attn[2 * 4 * 32 * 32];
__device__ uint32_t g_aouth[2 * 16384 * 64];  // attn@v as [b][p][c/2] half2

__constant__ int   c_src[16] = {0,1,2,3, 1,0,3,2, 2,3,0,1, 3,2,1,0};
__constant__ float c_sgn[16] = {1,-1,-1,-1, 1,1,-1,1, 1,1,1,-1, 1,-1,1,1};

static __device__ __forceinline__ void mma16(float* d, const uint32_t* a,
                                             uint32_t b0, uint32_t b1) {
    asm volatile(
        "mma.sync.aligned.m16n8k16.row.col.f32.f16.f16.f32 "
        "{%0,%1,%2,%3}, {%4,%5,%6,%7}, {%8,%9}, {%0,%1,%2,%3};"
        : "+f"(d[0]), "+f"(d[1]), "+f"(d[2]), "+f"(d[3])
        : "r"(a[0]), "r"(a[1]), "r"(a[2]), "r"(a[3]), "r"(b0), "r"(b1));
}

// ---------------- build quaternion weight matrices ----------------
// frag layouts: idx = ((octile*NK + kstep)*32 + lane)*4 + j, halves e=0,1
//   oc = octile*16 + (lane>>2) + (j&1)*8
//   channel offset within kstep (k-permuted for LDS.64 B loads):
//   kk = kstep*16 + 4*(lane&3) + e + (j>>1)*2
__global__ void build_weights(
    const float* __restrict__ qr, const float* __restrict__ qi,
    const float* __restrict__ qj, const float* __restrict__ qk,
    const float* __restrict__ dr, const float* __restrict__ di,
    const float* __restrict__ dj, const float* __restrict__ dk,
    const float* __restrict__ pr, const float* __restrict__ pi,
    const float* __restrict__ pj, const float* __restrict__ pk)
{
    const float* qb[4] = {qr, qi, qj, qk};
    const float* db[4] = {dr, di, dj, dk};
    const float* pb[4] = {pr, pi, pj, pk};
    const int N1 = 24 * 8 * 128;
    const int NH = 24 * 216 * 128;
    const int NPH = 8 * 8 * 128;
    int total = N1 + NH + NPH;
    for (int i = blockIdx.x * blockDim.x + threadIdx.x; i < total;
         i += gridDim.x * blockDim.x) {
        if (i < N1) {
            int j = i & 3, lane = (i >> 2) & 31;
            int rest = i >> 7;
            int kstep = rest % 8, octile = rest / 8;
            int oc = octile * 16 + (lane >> 2) + (j & 1) * 8;
            float w[2];
            #pragma unroll
            for (int e = 0; e < 2; e++) {
                int c = kstep * 16 + 4 * (lane & 3) + e + ((j >> 1) << 1);
                int br = oc / 96, oo = oc % 96, bc = c / 32, cc = c % 32;
                int hi = br * 4 + bc;
                w[e] = c_sgn[hi] * qb[c_src[hi]][oo * 32 + cc];
            }
            __half2 h = __floats2half2_rn(w[0], w[1]);
            g_W1h[i] = *(uint32_t*)&h;
        } else if (i < N1 + NH) {
            int idx = i - N1;
            int j = idx & 3, lane = (idx >> 2) & 31;
            int rest = idx >> 7;
            int kstep = rest % 216, octile = rest / 216;
            int oc = octile * 16 + (lane >> 2) + (j & 1) * 8;
            float w[2];
            #pragma unroll
            for (int e = 0; e < 2; e++) {
                int kk = kstep * 16 + 4 * (lane & 3) + e + ((j >> 1) << 1);
                int kx = kk / 1152, rem = kk % 1152;
                int ky = rem / 384, c = rem % 384;
                int br = oc / 96, oo = oc % 96, bc = c / 96, cc = c % 96;
                int hi = br * 4 + bc;
                w[e] = c_sgn[hi] * db[c_src[hi]][(oo * 96 + cc) * 9 + ky * 3 + kx];
            }
            __half2 h = __floats2half2_rn(w[0], w[1]);
            g_Wh[idx] = *(uint32_t*)&h;
        } else {
            int idx = i - N1 - NH;
            int j = idx & 3, lane = (idx >> 2) & 31;
            int rest = idx >> 7;
            int kstep = rest % 8, octile = rest / 8;
            int oc = octile * 16 + (lane >> 2) + (j & 1) * 8;
            float w[2];
            #pragma unroll
            for (int e = 0; e < 2; e++) {
                int c = kstep * 16 + 4 * (lane & 3) + e + ((j >> 1) << 1);
                int br = oc / 32, oo = oc % 32, bc = c / 32, cc = c % 32;
                int hi = br * 4 + bc;
                w[e] = c_sgn[hi] * pb[c_src[hi]][oo * 32 + cc];
            }
            __half2 h = __floats2half2_rn(w[0], w[1]);
            g_Wph[idx] = *(uint32_t*)&h;
        }
    }
}

// ---------------- transpose input x: NCHW fp32 -> [b][p][c/2] half2 ----------------
__global__ __launch_bounds__(256) void transpose_xin(const float* __restrict__ X,
                                                     uint32_t* __restrict__ Xh)
{
    __shared__ float t[32][65];
    int p0 = blockIdx.x * 64, c0 = blockIdx.y * 32, b = blockIdx.z;
    const float* src = X + ((size_t)b * 128 + c0) * 16384 + p0;
    for (int i = threadIdx.x; i < 2048; i += 256) {
        int c = i >> 6, p = i & 63;
        t[c][p] = src[(size_t)c * 16384 + p];
    }
    __syncthreads();
    uint32_t* dst = Xh + (size_t)b * 1048576 + (size_t)p0 * 64 + (c0 >> 1);
    for (int i = threadIdx.x; i < 1024; i += 256) {
        int p = i >> 4, cp = i & 15;
        __half2 h = __floats2half2_rn(t[cp * 2][p], t[cp * 2 + 1][p]);
        dst[(size_t)p * 64 + cp] = *(uint32_t*)&h;
    }
}

// ---------------- qkv 1x1: fp16 mma GEMM -> transposed fp16 output ----------------
// Grid (128 pblock, 3 mblock, 2 b); 256 thr; warp tile 32m x 64p; K=128.
__global__ __launch_bounds__(256, 2) void gemm_qkv_mma(
    const uint32_t* __restrict__ Xh, const float* __restrict__ bias,
    uint32_t* __restrict__ Xt)
{
    __shared__ __align__(16) char gsm[128 * 130 * 2];   // union: in_s / ep
    uint32_t* in_s = (uint32_t*)gsm;                    // [128p][stride 24 u32]
    __half* ep = (__half*)gsm;                          // [128p][130]
    int tid = threadIdx.x, wid = tid >> 5, lane = tid & 31;
    int pblk = blockIdx.x, mb = blockIdx.y, b = blockIdx.z;
    int oct0 = mb * 8 + (wid >> 1) * 2;
    int xw = (wid & 1) * 64;

    const uint4* W4 = (const uint4*)g_W1h;
    const uint4* pW0 = W4 + (size_t)(oct0 * 8) * 32 + lane;
    const uint4* pW1 = pW0 + (size_t)8 * 32;

    float acc[2][8][4] = {};
    uint4 Abuf[2][2];
    Abuf[0][0] = pW0[0];
    Abuf[0][1] = pW1[0];

    const uint4* Xrow = (const uint4*)(Xh + ((size_t)b * 16384 + (size_t)pblk * 128) * 64);
    for (int cb = 0; cb < 4; cb++) {
        __syncthreads();
        for (int idx = tid; idx < 512; idx += 256) {
            int row = idx >> 2, q = idx & 3;
            uint4 v = Xrow[(size_t)row * 16 + cb * 4 + q];
            *(uint4*)&in_s[row * 24 + q * 4] = v;
        }
        __syncthreads();
        #pragma unroll
        for (int ks = 0; ks < 2; ks++) {
            const int cidx = cb * 2 + ks;
            const int pb = cidx & 1;
            if (cidx < 7) {
                int nstep = cidx + 1;
                Abuf[pb ^ 1][0] = pW0[(size_t)nstep * 32];
                Abuf[pb ^ 1][1] = pW1[(size_t)nstep * 32];
            }
            uint4 A0v = Abuf[pb][0];
            uint4 A1v = Abuf[pb][1];
            uint32_t a0[4] = {A0v.x, A0v.y, A0v.z, A0v.w};
            uint32_t a1[4] = {A1v.x, A1v.y, A1v.z, A1v.w};
            int cbase = ks * 8 + 2 * (lane & 3);
            int xbase = xw + (lane >> 2);
            #pragma unroll
            for (int n = 0; n < 8; n++) {
                int xr = xbase + n * 8;
                uint2 bb = *(const uint2*)&in_s[xr * 24 + cbase];
                mma16(acc[0][n], a0, bb.x, bb.y);
                mma16(acc[1][n], a1, bb.x, bb.y);
            }
        }
    }

    __syncthreads();
    #pragma unroll
    for (int m = 0; m < 2; m++) {
        int cl = ((wid >> 1) * 2 + m) * 16 + (lane >> 2);
        float bv0 = bias[mb * 128 + cl];
        float bv1 = bias[mb * 128 + cl + 8];
        #pragma unroll
        for (int n = 0; n < 8; n++) {
            int p = xw + n * 8 + (lane & 3) * 2;
            ep[p * 130 + cl]           = __float2half(acc[m][n][0] + bv0);
            ep[(p + 1) * 130 + cl]     = __float2half(acc[m][n][1] + bv0);
            ep[p * 130 + cl + 8]       = __float2half(acc[m][n][2] + bv1);
            ep[(p + 1) * 130 + cl + 8] = __float2half(acc[m][n][3] + bv1);
        }
    }
    __syncthreads();
    uint32_t* dst = Xt + ((size_t)b * 16384 + (size_t)pblk * 128) * 192 + mb * 64;
    for (int idx = tid; idx < 8192; idx += 256) {
        int p = idx >> 6, cw = idx & 63;
        uint32_t v = *(const uint32_t*)&ep[p * 130 + cw * 2];
        dst[(size_t)p * 192 + cw] = v;
    }
}

// ---------------- 3x3 conv: fp16 m16n8k16 implicit GEMM, LDS.64 B loads ----------------
__global__ __launch_bounds__(256, 2) void conv3x3_mma(
    const uint32_t* __restrict__ Xt, const float* __restrict__ bias,
    float* __restrict__ Y)
{
    __shared__ __align__(16) uint32_t in_s[130 * 24];  // [x+1][c half2], stride 24
    int tid = threadIdx.x, wid = tid >> 5, lane = tid & 31;
    int y0 = blockIdx.x, by = blockIdx.y, b = blockIdx.z;
    int oct0 = by * 8 + (wid >> 1) * 2;
    int xw = (wid & 1) * 64;

    const uint4* Wh4 = (const uint4*)g_Wh;
    const uint4* pW0 = Wh4 + (size_t)(oct0 * 216) * 32 + lane;
    const uint4* pW1 = pW0 + (size_t)216 * 32;

    float acc[2][8][4] = {};
    uint4 Abuf[2][2];
    Abuf[0][0] = pW0[0];
    Abuf[0][1] = pW1[0];

    for (int ky = 0; ky < 3; ky++) {
        int yin = y0 - 1 + ky;
        bool okrow = ((unsigned)yin < 128u);
        const uint4* Xrow = (const uint4*)(Xt + ((size_t)b * 16384 + (size_t)yin * 128) * 192);
        for (int cb = 0; cb < 12; cb++) {
            __syncthreads();
            for (int idx = tid; idx < 520; idx += 256) {
                int row = idx >> 2, q = idx & 3;
                int x = row - 1;
                uint4 v = make_uint4(0u, 0u, 0u, 0u);
                if (okrow && (unsigned)x < 128u)
                    v = Xrow[(size_t)x * 48 + cb * 4 + q];
                *(uint4*)&in_s[row * 24 + q * 4] = v;
            }
            __syncthreads();
            #pragma unroll
            for (int kx = 0; kx < 3; kx++) {
                #pragma unroll
                for (int ks = 0; ks < 2; ks++) {
                    const int cidx = kx * 2 + ks;
                    const int pb = cidx & 1;
                    int nstep; bool valid = true;
                    if (cidx < 5) {
                        int nx = (cidx + 1) >> 1, nk = (cidx + 1) & 1;
                        nstep = nx * 72 + ky * 24 + cb * 2 + nk;
                    } else {
                        int cbn = cb + 1, kyn = ky;
                        if (cbn == 12) { cbn = 0; kyn++; }
                        valid = kyn < 3;
                        nstep = kyn * 24 + cbn * 2;
                    }
                    if (valid) {
                        Abuf[pb ^ 1][0] = pW0[(size_t)nstep * 32];
                        Abuf[pb ^ 1][1] = pW1[(size_t)nstep * 32];
                    }
                    uint4 A0v = Abuf[pb][0];
                    uint4 A1v = Abuf[pb][1];
                    uint32_t a0[4] = {A0v.x, A0v.y, A0v.z, A0v.w};
                    uint32_t a1[4] = {A1v.x, A1v.y, A1v.z, A1v.w};
                    int cbase = ks * 8 + 2 * (lane & 3);
                    int xbase = xw + (lane >> 2) + kx;
                    #pragma unroll
                    for (int n = 0; n < 8; n++) {
                        int xr = xbase + n * 8;
                        uint2 bb = *(const uint2*)&in_s[xr * 24 + cbase];
                        mma16(acc[0][n], a0, bb.x, bb.y);
                        mma16(acc[1][n], a1, bb.x, bb.y);
                    }
                }
            }
        }
    }

    float* Yb = Y + (size_t)b * 384 * 16384 + (size_t)y0 * 128;
    #pragma unroll
    for (int m = 0; m < 2; m++) {
        int ocb = (oct0 + m) * 16 + (lane >> 2);
        float bv0 = bias[ocb];
        float bv1 = bias[ocb + 8];
        #pragma unroll
        for (int n = 0; n < 8; n++) {
            int x = xw + n * 8 + (lane & 3) * 2;
            float2 v0 = make_float2(acc[m][n][0] + bv0, acc[m][n][1] + bv0);
            float2 v1 = make_float2(acc[m][n][2] + bv1, acc[m][n][3] + bv1);
            *(float2*)&Yb[(size_t)ocb * 16384 + x] = v0;
            *(float2*)&Yb[(size_t)(ocb + 8) * 16384 + x] = v1;
        }
    }
}

// ---------------- po 1x1: fp16 mma GEMM -> fp32 NCHW output ----------------
// Grid (128 pblock, 1, 2 b); K=128, M=128.
__global__ __launch_bounds__(256, 2) void gemm_po_mma(
    const uint32_t* __restrict__ Ah, const float* __restrict__ bias,
    float* __restrict__ Y)
{
    __shared__ __align__(16) uint32_t in_s[128 * 24];
    int tid = threadIdx.x, wid = tid >> 5, lane = tid & 31;
    int pblk = blockIdx.x, b = blockIdx.z;
    int oct0 = (wid >> 1) * 2;
    int xw = (wid & 1) * 64;

    const uint4* W4 = (const uint4*)g_Wph;
    const uint4* pW0 = W4 + (size_t)(oct0 * 8) * 32 + lane;
    const uint4* pW1 = pW0 + (size_t)8 * 32;

    float acc[2][8][4] = {};
    uint4 Abuf[2][2];
    Abuf[0][0] = pW0[0];
    Abuf[0][1] = pW1[0];

    const uint4* Xrow = (const uint4*)(Ah + ((size_t)b * 16384 + (size_t)pblk * 128) * 64);
    for (int cb = 0; cb < 4; cb++) {
        __syncthreads();
        for (int idx = tid; idx < 512; idx += 256) {
            int row = idx >> 2, q = idx & 3;
            uint4 v = Xrow[(size_t)row * 16 + cb * 4 + q];
            *(uint4*)&in_s[row * 24 + q * 4] = v;
        }
        __syncthreads();
        #pragma unroll
        for (int ks = 0; ks < 2; ks++) {
            const int cidx = cb * 2 + ks;
            const int pb = cidx & 1;
            if (cidx < 7) {
                int nstep = cidx + 1;
                Abuf[pb ^ 1][0] = pW0[(size_t)nstep * 32];
                Abuf[pb ^ 1][1] = pW1[(size_t)nstep * 32];
            }
            uint4 A0v = Abuf[pb][0];
            uint4 A1v = Abuf[pb][1];
            uint32_t a0[4] = {A0v.x, A0v.y, A0v.z, A0v.w};
            uint32_t a1[4] = {A1v.x, A1v.y, A1v.z, A1v.w};
            int cbase = ks * 8 + 2 * (lane & 3);
            int xbase = xw + (lane >> 2);
            #pragma unroll
            for (int n = 0; n < 8; n++) {
                int xr = xbase + n * 8;
                uint2 bb = *(const uint2*)&in_s[xr * 24 + cbase];
                mma16(acc[0][n], a0, bb.x, bb.y);
                mma16(acc[1][n], a1, bb.x, bb.y);
            }
        }
    }

    float* Yb = Y + (size_t)b * 128 * 16384 + (size_t)pblk * 128;
    #pragma unroll
    for (int m = 0; m < 2; m++) {
        int ocb = (oct0 + m) * 16 + (lane >> 2);
        float bv0 = bias[ocb];
        float bv1 = bias[ocb + 8];
        #pragma unroll
        for (int n = 0; n < 8; n++) {
            int x = xw + n * 8 + (lane & 3) * 2;
            float2 v0 = make_float2(acc[m][n][0] + bv0, acc[m][n][1] + bv0);
            float2 v1 = make_float2(acc[m][n][2] + bv1, acc[m][n][3] + bv1);
            *(float2*)&Yb[(size_t)ocb * 16384 + x] = v0;
            *(float2*)&Yb[(size_t)(ocb + 8) * 16384 + x] = v1;
        }
    }
}

// ---------------- L2 norms ----------------
__global__ void norm_kernel(const float* __restrict__ Q2, float* __restrict__ rn)
{
    int b = blockIdx.x >> 8, ch = blockIdx.x & 255;
    const float* p = Q2 + ((size_t)b * 384 + ch) * 16384;
    float s = 0.f;
    for (int i = threadIdx.x; i < 16384; i += 256) { float v = p[i]; s += v * v; }
    __shared__ float red[8];
    #pragma unroll
    for (int o = 16; o; o >>= 1) s += __shfl_xor_sync(~0u, s, o);
    if ((threadIdx.x & 31) == 0) red[threadIdx.x >> 5] = s;
    __syncthreads();
    if (threadIdx.x < 8) {
        s = red[threadIdx.x];
        #pragma unroll
        for (int o = 4; o; o >>= 1) s += __shfl_xor_sync(0xffu, s, o);
        if (threadIdx.x == 0) rn[blockIdx.x] = 1.f / fmaxf(sqrtf(s), 1e-12f);
    }
}

// ---------------- QK^T partials ----------------
__global__ __launch_bounds__(256) void attn_qk(const float* __restrict__ Q2)
{
    int slice = blockIdx.x & 31, h = (blockIdx.x >> 5) & 3, b = blockIdx.x >> 7;
    __shared__ float qs[32 * 129], ks[32 * 129];
    int t = threadIdx.x;
    int c0 = t >> 3, d0 = (t & 7) << 2;
    const float* qp = Q2 + ((size_t)b * 384 + h * 32) * 16384;
    const float* kp = Q2 + ((size_t)b * 384 + 128 + h * 32) * 16384;
    float acc[4] = {};
    int sbase = slice * 512;
    for (int ch = 0; ch < 4; ch++) {
        int s0 = sbase + ch * 128;
        for (int i = t; i < 4096; i += 256) {
            int c = i >> 7, s = i & 127;
            qs[c * 129 + s] = qp[(size_t)c * 16384 + s0 + s];
            ks[c * 129 + s] = kp[(size_t)c * 16384 + s0 + s];
        }
        __syncthreads();
        #pragma unroll 4
        for (int s = 0; s < 128; s++) {
            float qv = qs[c0 * 129 + s];
            #pragma unroll
            for (int j = 0; j < 4; j++) acc[j] += qv * ks[(d0 + j) * 129 + s];
        }
        __syncthreads();
    }
    float* pp = g_part + (((size_t)(b * 4 + h) * 32 + slice) * 1024) + c0 * 32 + d0;
    #pragma unroll
    for (int j = 0; j < 4; j++) pp[j] = acc[j];
}

// ---------------- softmax ----------------
__global__ __launch_bounds__(1024) void softmax_kernel(
    const float* __restrict__ rn, const float* __restrict__ temp)
{
    int bh = blockIdx.x;
    int b = bh >> 2, h = bh & 3;
    int c = threadIdx.x >> 5, d = threadIdx.x & 31;
    const float* base = g_part + (size_t)bh * 32768 + c * 32 + d;
    float v = 0.f;
    #pragma unroll 8
    for (int sl = 0; sl < 32; sl++) v += base[(size_t)sl * 1024];
    float rq = rn[b * 256 + h * 32 + c];
    float rk = rn[b * 256 + 128 + h * 32 + d];
    v = v * rq * rk * temp[h];
    float mx = v;
    #pragma unroll
    for (int o = 16; o; o >>= 1) mx = fmaxf(mx, __shfl_xor_sync(~0u, mx, o));
    float e = __expf(v - mx);
    float sum = e;
    #pragma unroll
    for (int o = 16; o; o >>= 1) sum += __shfl_xor_sync(~0u, sum, o);
    g_attn[(size_t)bh * 1024 + c * 32 + d] = e / sum;
}

// ---------------- out = attn @ v -> transposed fp16 [p][c] ----------------
__global__ __launch_bounds__(256) void attn_v(const float* __restrict__ Q2,
                                              uint32_t* __restrict__ Aout)
{
    __shared__ float A[1024];
    __shared__ __half ep[256 * 34];
    int st = blockIdx.x & 63, h = (blockIdx.x >> 6) & 3, b = blockIdx.x >> 8;
    int t = threadIdx.x;
    for (int i = t; i < 1024; i += 256) A[i] = g_attn[(size_t)(b * 4 + h) * 1024 + i];
    __syncthreads();
    int s = st * 256 + t;
    const float* vp = Q2 + ((size_t)b * 384 + 256 + h * 32) * 16384 + s;
    float vr[32];
    #pragma unroll
    for (int d = 0; d < 32; d++) vr[d] = vp[(size_t)d * 16384];
    #pragma unroll
    for (int c = 0; c < 32; c++) {
        float sum = 0.f;
        #pragma unroll
        for (int d = 0; d < 32; d++) sum += A[c * 32 + d] * vr[d];
        ep[t * 34 + c] = __float2half(sum);
    }
    __syncthreads();
    uint32_t* dst = Aout + ((size_t)b * 16384 + (size_t)st * 256) * 64 + h * 16;
    for (int idx = t; idx < 4096; idx += 256) {
        int p = idx >> 4, cw = idx & 15;
        dst[(size_t)p * 64 + cw] = *(const uint32_t*)&ep[p * 34 + cw * 2];
    }
}

// ---------------- launch ----------------
extern "C" void kernel_launch(void* const* d_in, const int* in_sizes, int n_in,
                              void* d_out, int out_size)
{
    const float* x    = (const float*)d_in[0];
    const float* qr   = (const float*)d_in[1];
    const float* qi   = (const float*)d_in[2];
    const float* qj   = (const float*)d_in[3];
    const float* qk   = (const float*)d_in[4];
    const float* qkvb = (const float*)d_in[5];
    const float* dr   = (const float*)d_in[6];
    const float* di   = (const float*)d_in[7];
    const float* dj   = (const float*)d_in[8];
    const float* dk   = (const float*)d_in[9];
    const float* dwb  = (const float*)d_in[10];
    const float* pr   = (const float*)d_in[11];
    const float* pi   = (const float*)d_in[12];
    const float* pj   = (const float*)d_in[13];
    const float* pk   = (const float*)d_in[14];
    const float* pob  = (const float*)d_in[15];
    const float* temp = (const float*)d_in[16];
    float* out = (float*)d_out;

    float *pQ2, *pRn;
    uint32_t *pXh, *pXt, *pAh;
    cudaGetSymbolAddress((void**)&pQ2, g_qkv2);
    cudaGetSymbolAddress((void**)&pRn, g_rnorm);
    cudaGetSymbolAddress((void**)&pXh, g_xh);
    cudaGetSymbolAddress((void**)&pXt, g_xth);
    cudaGetSymbolAddress((void**)&pAh, g_aouth);

    build_weights<<<512, 256>>>(qr, qi, qj, qk, dr, di, dj, dk, pr, pi, pj, pk);
    transpose_xin<<<dim3(256, 4, 2), 256>>>(x, pXh);
    gemm_qkv_mma<<<dim3(128, 3, 2), 256>>>(pXh, qkvb, pXt);
    conv3x3_mma<<<dim3(128, 3, 2), 256>>>(pXt, dwb, pQ2);
    norm_kernel<<<512, 256>>>(pQ2, pRn);
    attn_qk<<<256, 256>>>(pQ2);
    softmax_kernel<<<8, 1024>>>(pRn, temp);
    attn_v<<<512, 256>>>(pQ2, pAh);
    gemm_po_mma<<<dim3(128, 1, 2), 256>>>(pAh, pob, out);
}